// round 11
// baseline (speedup 1.0000x reference)
#include <cuda_runtime.h>
#include <cuda_bf16.h>
#include <stdint.h>
#include <math.h>

// ---------------------------------------------------------------------------
// MultiModalAttention (sm_103 base target): HMMA m16n8k16 bf16, 3-term split.
// Round 11: BK=64 / NSTAGE=2 (one post-barrier LDSM ramp per 64-k instead of
// two per 2x32-k). R6/R10 inner schedule otherwise verbatim. Launch order puts
// the merged projection GEMM at ncu capture slot #4.
// ---------------------------------------------------------------------------

#define BATCH   8192
#define IMGDIM  2048
#define QDIM    768
#define HDIM    1024
#define H3      3072
#define B2      16384
#define NHEADS  16
#define HD      64

#define BM 256
#define BN 128
#define BK 64
#define KS_BYTES 144                      // 64 bf16 = 128B padded to 144B
#define ARR_A (BM * KS_BYTES)             // 36864
#define ARR_B (BN * KS_BYTES)             // 18432
#define OFF_AH 0
#define OFF_AL (ARR_A)
#define OFF_BH (2 * ARR_A)
#define OFF_BL (2 * ARR_A + ARR_B)
#define STAGE_BYTES (2 * ARR_A + 2 * ARR_B)   // 110592
#define SMEM_BYTES (2 * STAGE_BYTES)          // 221184 (fits 227KB limit)

// ---------------- device scratch ---------------------------------------------
__device__ float g_qkv[(size_t)B2 * H3];
__device__ float g_o2 [(size_t)B2 * HDIM];

__device__ __nv_bfloat16 g_f1h[(size_t)BATCH * IMGDIM], g_f1l[(size_t)BATCH * IMGDIM];
__device__ __nv_bfloat16 g_f2h[(size_t)BATCH * QDIM],  g_f2l[(size_t)BATCH * QDIM];
__device__ __nv_bfloat16 g_xh [(size_t)B2 * HDIM],     g_xl [(size_t)B2 * HDIM];
__device__ __nv_bfloat16 g_ah [(size_t)B2 * HDIM],     g_al [(size_t)B2 * HDIM];
__device__ __nv_bfloat16 g_w1h[(size_t)HDIM * IMGDIM], g_w1l[(size_t)HDIM * IMGDIM];
__device__ __nv_bfloat16 g_w2h[(size_t)HDIM * QDIM],   g_w2l[(size_t)HDIM * QDIM];
__device__ __nv_bfloat16 g_wqh[(size_t)H3 * HDIM],     g_wql[(size_t)H3 * HDIM];
__device__ __nv_bfloat16 g_woh[(size_t)HDIM * HDIM],   g_wol[(size_t)HDIM * HDIM];

// ---------------- helpers ------------------------------------------------------
__device__ __forceinline__ uint32_t smem_u32(const void* p) {
    return (uint32_t)__cvta_generic_to_shared(p);
}
__device__ __forceinline__ void cp16(uint32_t s, const void* g) {
    asm volatile("cp.async.cg.shared.global [%0], [%1], 16;"
                 :: "r"(s), "l"(__cvta_generic_to_global(g)) : "memory");
}
#define LDMX4(r, addr) \
    asm volatile("ldmatrix.sync.aligned.m8n8.x4.shared.b16 {%0,%1,%2,%3}, [%4];" \
        : "=r"((r)[0]), "=r"((r)[1]), "=r"((r)[2]), "=r"((r)[3]) : "r"(addr))
#define MMA16816(c, a, b0, b1) \
    asm volatile("mma.sync.aligned.m16n8k16.row.col.f32.bf16.bf16.f32 " \
        "{%0,%1,%2,%3}, {%4,%5,%6,%7}, {%8,%9}, {%0,%1,%2,%3};" \
        : "+f"((c)[0]), "+f"((c)[1]), "+f"((c)[2]), "+f"((c)[3]) \
        : "r"((a)[0]), "r"((a)[1]), "r"((a)[2]), "r"((a)[3]), "r"(b0), "r"(b1))

// ---------------- stage loader (512 threads, 12 cp.async each) ----------------
// Per stage: Ah/Al 256 rows x 8 chunks, Bh/Bl 128 rows x 8 chunks (16B chunks).
__device__ __forceinline__ void load_stage(
    uint32_t st, int tid,
    const __nv_bfloat16* __restrict__ Ah, const __nv_bfloat16* __restrict__ Al,
    const __nv_bfloat16* __restrict__ Bh, const __nv_bfloat16* __restrict__ Bl,
    int bm, int bn, int K, int k0)
{
    const int q  = tid & 7;      // 0..7 chunk within row
    const int rb = tid >> 3;     // 0..63
    #pragma unroll
    for (int t = 0; t < 12; t++) {
        const __nv_bfloat16* g;
        uint32_t sa;
        if (t < 4) {
            const int r = t * 64 + rb;                 // 0..255
            g  = Ah + (size_t)(bm + r) * K + k0 + q * 8;
            sa = st + OFF_AH + (uint32_t)r * KS_BYTES + q * 16;
        } else if (t < 8) {
            const int r = (t - 4) * 64 + rb;
            g  = Al + (size_t)(bm + r) * K + k0 + q * 8;
            sa = st + OFF_AL + (uint32_t)r * KS_BYTES + q * 16;
        } else if (t < 10) {
            const int r = (t - 8) * 64 + rb;           // 0..127
            g  = Bh + (size_t)(bn + r) * K + k0 + q * 8;
            sa = st + OFF_BH + (uint32_t)r * KS_BYTES + q * 16;
        } else {
            const int r = (t - 10) * 64 + rb;
            g  = Bl + (size_t)(bn + r) * K + k0 + q * 8;
            sa = st + OFF_BL + (uint32_t)r * KS_BYTES + q * 16;
        }
        cp16(sa, g);
    }
    asm volatile("cp.async.commit_group;" ::: "memory");
}

// ---------------- shared GEMM body (R6 schedule, BK=64, 2 stages) --------------
__device__ __forceinline__ void gemm_body(
    const __nv_bfloat16* __restrict__ Ah, const __nv_bfloat16* __restrict__ Al,
    const __nv_bfloat16* __restrict__ Bh, const __nv_bfloat16* __restrict__ Bl,
    const float* __restrict__ bias,
    float* __restrict__ outF, __nv_bfloat16* __restrict__ outH,
    __nv_bfloat16* __restrict__ outL,
    int N, int K, int row_mul, int row_off, int bm, int bn, uint32_t sb)
{
    const int tid   = threadIdx.x;
    const int wid   = tid >> 5;
    const int lane  = tid & 31;
    const int warpM = wid >> 2;      // 0..3 -> 64 rows each
    const int warpN = wid & 3;       // 0..3 -> 32 cols each

    float c[4][4][4];                // 64 regs
    #pragma unroll
    for (int i = 0; i < 4; i++)
        #pragma unroll
        for (int j = 0; j < 4; j++)
            #pragma unroll
            for (int k = 0; k < 4; k++) c[i][j][k] = 0.0f;

    const int NT = K / BK;
    load_stage(sb,               tid, Ah, Al, Bh, Bl, bm, bn, K, 0);
    load_stage(sb + STAGE_BYTES, tid, Ah, Al, Bh, Bl, bm, bn, K, BK);

    const int g8 = lane >> 3, lr = lane & 7;
    const int a_row = warpM * 64 + ((g8 & 1) ? 8 : 0) + lr;   // + mt*16
    const int a_kb  = (g8 >> 1) ? 16 : 0;
    const int b_row = warpN * 32 + ((g8 >> 1) ? 8 : 0) + lr;  // + n16*16
    const int b_kb  = (g8 & 1) ? 16 : 0;

    for (int kt = 0; kt < NT; kt++) {
        if (kt + 1 < NT) asm volatile("cp.async.wait_group 1;" ::: "memory");
        else             asm volatile("cp.async.wait_group 0;" ::: "memory");
        __syncthreads();

        const uint32_t st = sb + (uint32_t)(kt & 1) * STAGE_BYTES;
        #pragma unroll
        for (int kk = 0; kk < 4; kk++) {
            const int kb = kk * 32;   // 16 bf16 = 32 bytes per k16 step
            uint32_t ah[4][4], al[4][4];
            #pragma unroll
            for (int mt = 0; mt < 4; mt++) {
                uint32_t aaddr = st + OFF_AH +
                    (uint32_t)(a_row + mt * 16) * KS_BYTES + a_kb + kb;
                LDMX4(ah[mt], aaddr);
                LDMX4(al[mt], aaddr + ARR_A);
            }
            #pragma unroll
            for (int n16 = 0; n16 < 2; n16++) {
                uint32_t baddr = st + OFF_BH +
                    (uint32_t)(b_row + n16 * 16) * KS_BYTES + b_kb + kb;
                uint32_t bh[4], bl[4];
                LDMX4(bh, baddr);
                LDMX4(bl, baddr + ARR_B);
                #pragma unroll
                for (int mt = 0; mt < 4; mt++)
                    #pragma unroll
                    for (int nn = 0; nn < 2; nn++)
                        MMA16816(c[mt][n16 * 2 + nn], ah[mt], bh[2*nn], bh[2*nn+1]);
                #pragma unroll
                for (int mt = 0; mt < 4; mt++)
                    #pragma unroll
                    for (int nn = 0; nn < 2; nn++)
                        MMA16816(c[mt][n16 * 2 + nn], ah[mt], bl[2*nn], bl[2*nn+1]);
                #pragma unroll
                for (int mt = 0; mt < 4; mt++)
                    #pragma unroll
                    for (int nn = 0; nn < 2; nn++)
                        MMA16816(c[mt][n16 * 2 + nn], al[mt], bh[2*nn], bh[2*nn+1]);
            }
        }
        // all warps done reading stage kt&1 before it is overwritten
        __syncthreads();
        if (kt + 2 < NT)
            load_stage(st, tid, Ah, Al, Bh, Bl, bm, bn, K, (kt + 2) * BK);
    }

    // ---- epilogue ----
    const int quad = lane >> 2;
    const int tq   = lane & 3;
    #pragma unroll
    for (int nt = 0; nt < 4; nt++) {
        const int col = bn + warpN * 32 + nt * 8 + tq * 2;
        float bv0 = 0.0f, bv1 = 0.0f;
        if (bias) { bv0 = bias[col]; bv1 = bias[col + 1]; }
        #pragma unroll
        for (int mt = 0; mt < 4; mt++) {
            #pragma unroll
            for (int half = 0; half < 2; half++) {
                const int grow = bm + warpM * 64 + mt * 16 + half * 8 + quad;
                const size_t off = ((size_t)grow * row_mul + row_off) * N + col;
                float v0 = c[mt][nt][2 * half + 0] + bv0;
                float v1 = c[mt][nt][2 * half + 1] + bv1;
                if (outF) *(float2*)(outF + off) = make_float2(v0, v1);
                if (outH) {
                    __nv_bfloat16 h0 = __float2bfloat16(v0);
                    __nv_bfloat16 h1 = __float2bfloat16(v1);
                    __nv_bfloat162 hp; hp.x = h0; hp.y = h1;
                    *(__nv_bfloat162*)(outH + off) = hp;
                    __nv_bfloat162 lp;
                    lp.x = __float2bfloat16(v0 - __bfloat162float(h0));
                    lp.y = __float2bfloat16(v1 - __bfloat162float(h1));
                    *(__nv_bfloat162*)(outL + off) = lp;
                }
            }
        }
    }
}

// ---------------- GEMM kernels -------------------------------------------------
__global__ void __launch_bounds__(512, 1)
gemm_hmma(const __nv_bfloat16* __restrict__ Ah, const __nv_bfloat16* __restrict__ Al,
          const __nv_bfloat16* __restrict__ Bh, const __nv_bfloat16* __restrict__ Bl,
          const float* __restrict__ bias, float* __restrict__ outF,
          int N, int K)
{
    extern __shared__ char smem[];
    gemm_body(Ah, Al, Bh, Bl, bias, outF, nullptr, nullptr,
              N, K, 1, 0, blockIdx.y * BM, blockIdx.x * BN, smem_u32(smem));
}

// merged f1/f2 projection: blockIdx.z = modality (0: f1@W1+b1, 1: f2@W2+b2)
__global__ void __launch_bounds__(512, 1)
gemm_proj(const __nv_bfloat16* __restrict__ f1h, const __nv_bfloat16* __restrict__ f1l,
          const __nv_bfloat16* __restrict__ w1h, const __nv_bfloat16* __restrict__ w1l,
          const float* __restrict__ b1,
          const __nv_bfloat16* __restrict__ f2h, const __nv_bfloat16* __restrict__ f2l,
          const __nv_bfloat16* __restrict__ w2h, const __nv_bfloat16* __restrict__ w2l,
          const float* __restrict__ b2,
          __nv_bfloat16* __restrict__ xh, __nv_bfloat16* __restrict__ xl)
{
    extern __shared__ char smem[];
    if (blockIdx.z == 0)
        gemm_body(f1h, f1l, w1h, w1l, b1, nullptr, xh, xl,
                  HDIM, IMGDIM, 2, 0, blockIdx.y * BM, blockIdx.x * BN,
                  smem_u32(smem));
    else
        gemm_body(f2h, f2l, w2h, w2l, b2, nullptr, xh, xl,
                  HDIM, QDIM, 2, 1, blockIdx.y * BM, blockIdx.x * BN,
                  smem_u32(smem));
}

// ---------------- elementwise split (activations) ----------------------------
__global__ void __launch_bounds__(256)
asplit(const float* __restrict__ x, __nv_bfloat16* __restrict__ h,
       __nv_bfloat16* __restrict__ l, size_t n)
{
    size_t i = ((size_t)blockIdx.x * 256 + threadIdx.x) * 4;
    if (i >= n) return;
    float4 v = *(const float4*)(x + i);
    __nv_bfloat16 h0 = __float2bfloat16(v.x), h1 = __float2bfloat16(v.y);
    __nv_bfloat16 h2 = __float2bfloat16(v.z), h3 = __float2bfloat16(v.w);
    __nv_bfloat162 hp0; hp0.x = h0; hp0.y = h1;
    __nv_bfloat162 hp1; hp1.x = h2; hp1.y = h3;
    *(__nv_bfloat162*)(h + i)     = hp0;
    *(__nv_bfloat162*)(h + i + 2) = hp1;
    __nv_bfloat162 lp0, lp1;
    lp0.x = __float2bfloat16(v.x - __bfloat162float(h0));
    lp0.y = __float2bfloat16(v.y - __bfloat162float(h1));
    lp1.x = __float2bfloat16(v.z - __bfloat162float(h2));
    lp1.y = __float2bfloat16(v.w - __bfloat162float(h3));
    *(__nv_bfloat162*)(l + i)     = lp0;
    *(__nv_bfloat162*)(l + i + 2) = lp1;
}

// ---------------- weight transpose+split ---------------------------------------
__global__ void __launch_bounds__(256)
wsplit_all(const float* __restrict__ W1, const float* __restrict__ W2,
           const float* __restrict__ Wq, const float* __restrict__ Wo,
           __nv_bfloat16* __restrict__ w1h, __nv_bfloat16* __restrict__ w1l,
           __nv_bfloat16* __restrict__ w2h, __nv_bfloat16* __restrict__ w2l,
           __nv_bfloat16* __restrict__ wqh, __nv_bfloat16* __restrict__ wql,
           __nv_bfloat16* __restrict__ woh, __nv_bfloat16* __restrict__ wol,
           int zbase)
{
    const float* W; __nv_bfloat16 *th, *tl; int K, N;
    switch (blockIdx.z + zbase) {
        case 0: W = W1; th = w1h; tl = w1l; K = IMGDIM; N = HDIM; break;
        case 1: W = W2; th = w2h; tl = w2l; K = QDIM;   N = HDIM; break;
        case 2: W = Wq; th = wqh; tl = wql; K = HDIM;   N = H3;   break;
        default:W = Wo; th = woh; tl = wol; K = HDIM;   N = HDIM; break;
    }
    const int n0 = blockIdx.x * 32, k0 = blockIdx.y * 32;
    if (n0 >= N || k0 >= K) return;

    __shared__ float tile[32][33];
    const int tx = threadIdx.x & 31, ty = threadIdx.x >> 5;
    #pragma unroll
    for (int i = ty; i < 32; i += 8)
        tile[i][tx] = W[(size_t)(k0 + i) * N + n0 + tx];
    __syncthreads();
    #pragma unroll
    for (int i = ty; i < 32; i += 8) {
        int n = n0 + i, k = k0 + tx;
        float v = tile[tx][i];
        __nv_bfloat16 hh = __float2bfloat16(v);
        th[(size_t)n * K + k] = hh;
        tl[(size_t)n * K + k] = __float2bfloat16(v - __bfloat162float(hh));
    }
}

// ---------------- attention (2x2 per head) + split output --------------------
__global__ void __launch_bounds__(128)
attn_kernel(const float* __restrict__ qkv, __nv_bfloat16* __restrict__ oh,
            __nv_bfloat16* __restrict__ ol)
{
    const int b = blockIdx.x;
    const int warp = threadIdx.x >> 5;
    const int lane = threadIdx.x & 31;
    const float scale = 0.125f;
    const size_t base0 = (size_t)(2 * b) * H3;
    const size_t base1 = base0 + H3;

    #pragma unroll
    for (int h = warp; h < NHEADS; h += 4) {
        const int off = h * HD + lane;
        float q0a = qkv[base0 + off],          q0b = qkv[base0 + off + 32];
        float k0a = qkv[base0 + HDIM + off],   k0b = qkv[base0 + HDIM + off + 32];
        float v0a = qkv[base0 + 2*HDIM + off], v0b = qkv[base0 + 2*HDIM + off + 32];
        float q1a = qkv[base1 + off],          q1b = qkv[base1 + off + 32];
        float k1a = qkv[base1 + HDIM + off],   k1b = qkv[base1 + HDIM + off + 32];
        float v1a = qkv[base1 + 2*HDIM + off], v1b = qkv[base1 + 2*HDIM + off + 32];

        float s00 = q0a * k0a + q0b * k0b;
        float s01 = q0a * k1a + q0b * k1b;
        float s10 = q1a * k0a + q1b * k0b;
        float s11 = q1a * k1a + q1b * k1b;
        #pragma unroll
        for (int d = 16; d; d >>= 1) {
            s00 += __shfl_xor_sync(0xffffffffu, s00, d);
            s01 += __shfl_xor_sync(0xffffffffu, s01, d);
            s10 += __shfl_xor_sync(0xffffffffu, s10, d);
            s11 += __shfl_xor_sync(0xffffffffu, s11, d);
        }
        s00 *= scale; s01 *= scale; s10 *= scale; s11 *= scale;

        float m0 = fmaxf(s00, s01), m1 = fmaxf(s10, s11);
        float e00 = __expf(s00 - m0), e01 = __expf(s01 - m0);
        float e10 = __expf(s10 - m1), e11 = __expf(s11 - m1);
        float inv0 = 1.0f / (e00 + e01), inv1 = 1.0f / (e10 + e11);
        float p00 = e00 * inv0, p01 = e01 * inv0;
        float p10 = e10 * inv1, p11 = e11 * inv1;

        float r0 = p00 * v0a + p01 * v1a;
        float r1 = p00 * v0b + p01 * v1b;
        float r2 = p10 * v0a + p11 * v1a;
        float r3 = p10 * v0b + p11 * v1b;

        size_t o0 = (size_t)(2 * b) * HDIM + h * HD + lane;
        size_t o1 = o0 + HDIM;
        __nv_bfloat16 h0 = __float2bfloat16(r0);
        __nv_bfloat16 h1 = __float2bfloat16(r1);
        __nv_bfloat16 h2 = __float2bfloat16(r2);
        __nv_bfloat16 h3 = __float2bfloat16(r3);
        oh[o0] = h0;      oh[o0 + 32] = h1;
        oh[o1] = h2;      oh[o1 + 32] = h3;
        ol[o0]      = __float2bfloat16(r0 - __bfloat162float(h0));
        ol[o0 + 32] = __float2bfloat16(r1 - __bfloat162float(h1));
        ol[o1]      = __float2bfloat16(r2 - __bfloat162float(h2));
        ol[o1 + 32] = __float2bfloat16(r3 - __bfloat162float(h3));
    }
}

// ---------------- LayerNorm(2048) + residual(hi+lo) ---------------------------
__global__ void __launch_bounds__(256)
ln_kernel(const float* __restrict__ o2,
          const __nv_bfloat16* __restrict__ xh, const __nv_bfloat16* __restrict__ xl,
          const float* __restrict__ gamma, const float* __restrict__ beta,
          float* __restrict__ out)
{
    const int b = blockIdx.x;
    const int tid = threadIdx.x;
    const float* x = o2 + (size_t)b * 2048;
    const __nv_bfloat16* rh = xh + (size_t)b * 2048;
    const __nv_bfloat16* rl = xl + (size_t)b * 2048;

    float vals[8];
    float sum = 0.0f, sq = 0.0f;
    #pragma unroll
    for (int i = 0; i < 8; i++) {
        float v = x[tid + i * 256];
        vals[i] = v; sum += v; sq += v * v;
    }
    #pragma unroll
    for (int d = 16; d; d >>= 1) {
        sum += __shfl_xor_sync(0xffffffffu, sum, d);
        sq  += __shfl_xor_sync(0xffffffffu, sq, d);
    }
    __shared__ float ssum[8], ssq[8];
    const int warp = tid >> 5, lane = tid & 31;
    if (lane == 0) { ssum[warp] = sum; ssq[warp] = sq; }
    __syncthreads();
    float tsum = 0.0f, tsq = 0.0f;
    #pragma unroll
    for (int w = 0; w < 8; w++) { tsum += ssum[w]; tsq += ssq[w]; }

    const float mu   = tsum * (1.0f / 2048.0f);
    const float var  = tsq * (1.0f / 2048.0f) - mu * mu;
    const float rinv = rsqrtf(var + 1e-5f);

    float* o = out + (size_t)b * 2048;
    #pragma unroll
    for (int i = 0; i < 8; i++) {
        int cx = tid + i * 256;
        float r = __bfloat162float(rh[cx]) + __bfloat162float(rl[cx]);
        o[cx] = (vals[i] - mu) * rinv * gamma[cx] + beta[cx] + r;
    }
}

// ---------------------------------------------------------------------------
extern "C" void kernel_launch(void* const* d_in, const int* in_sizes, int n_in,
                              void* d_out, int out_size)
{
    const float* features1 = (const float*)d_in[0];
    const float* features2 = (const float*)d_in[1];
    const float* W1    = (const float*)d_in[2];
    const float* b1    = (const float*)d_in[3];
    const float* W2    = (const float*)d_in[4];
    const float* b2    = (const float*)d_in[5];
    const float* Wqkv  = (const float*)d_in[6];
    const float* Wout  = (const float*)d_in[7];
    const float* bout  = (const float*)d_in[8];
    const float* gamma = (const float*)d_in[9];
    const float* beta  = (const float*)d_in[10];
    float* out = (float*)d_out;

    float *p_qkv, *p_o2;
    __nv_bfloat16 *p_f1h, *p_f1l, *p_f2h, *p_f2l, *p_xh, *p_xl, *p_ah, *p_al;
    __nv_bfloat16 *p_w1h, *p_w1l, *p_w2h, *p_w2l, *p_wqh, *p_wql, *p_woh, *p_wol;
    cudaGetSymbolAddress((void**)&p_qkv, g_qkv);
    cudaGetSymbolAddress((void**)&p_o2,  g_o2);
    cudaGetSymbolAddress((void**)&p_f1h, g_f1h); cudaGetSymbolAddress((void**)&p_f1l, g_f1l);
    cudaGetSymbolAddress((void**)&p_f2h, g_f2h); cudaGetSymbolAddress((void**)&p_f2l, g_f2l);
    cudaGetSymbolAddress((void**)&p_xh,  g_xh);  cudaGetSymbolAddress((void**)&p_xl,  g_xl);
    cudaGetSymbolAddress((void**)&p_ah,  g_ah);  cudaGetSymbolAddress((void**)&p_al,  g_al);
    cudaGetSymbolAddress((void**)&p_w1h, g_w1h); cudaGetSymbolAddress((void**)&p_w1l, g_w1l);
    cudaGetSymbolAddress((void**)&p_w2h, g_w2h); cudaGetSymbolAddress((void**)&p_w2l, g_w2l);
    cudaGetSymbolAddress((void**)&p_wqh, g_wqh); cudaGetSymbolAddress((void**)&p_wql, g_wql);
    cudaGetSymbolAddress((void**)&p_woh, g_woh); cudaGetSymbolAddress((void**)&p_wol, g_wol);

    cudaFuncSetAttribute(gemm_hmma, cudaFuncAttributeMaxDynamicSharedMemorySize,
                         SMEM_BYTES);
    cudaFuncSetAttribute(gemm_proj, cudaFuncAttributeMaxDynamicSharedMemorySize,
                         SMEM_BYTES);

    // ncu (-s 5 -c 1) empirically captures OUR 4th launch -> put proj there.
    asplit<<<(size_t)BATCH * IMGDIM / 1024, 256>>>(features1, p_f1h, p_f1l,
                                                   (size_t)BATCH * IMGDIM);       // 1
    asplit<<<(size_t)BATCH * QDIM / 1024, 256>>>(features2, p_f2h, p_f2l,
                                                 (size_t)BATCH * QDIM);           // 2
    wsplit_all<<<dim3(HDIM / 32, IMGDIM / 32, 2), 256>>>(
        W1, W2, Wqkv, Wout, p_w1h, p_w1l, p_w2h, p_w2l,
        p_wqh, p_wql, p_woh, p_wol, 0);                                           // 3
    // merged f1/f2 projections -> x hi/lo (profiled launch)
    gemm_proj<<<dim3(HDIM / BN, BATCH / BM, 2), 512, SMEM_BYTES>>>(
        p_f1h, p_f1l, p_w1h, p_w1l, b1,
        p_f2h, p_f2l, p_w2h, p_w2l, b2, p_xh, p_xl);                              // 4
    wsplit_all<<<dim3(H3 / 32, HDIM / 32, 2), 256>>>(
        W1, W2, Wqkv, Wout, p_w1h, p_w1l, p_w2h, p_w2l,
        p_wqh, p_wql, p_woh, p_wol, 2);                                           // 5
    // G3: x @ Wqkv -> qkv fp32
    gemm_hmma<<<dim3(H3 / BN, B2 / BM), 512, SMEM_BYTES>>>(
        p_xh, p_xl, p_wqh, p_wql, nullptr, p_qkv, H3, HDIM);                      // 6
    attn_kernel<<<BATCH, 128>>>(p_qkv, p_ah, p_al);                               // 7
    // G4: att @ Wout + bout -> o2 fp32
    gemm_hmma<<<dim3(HDIM / BN, B2 / BM), 512, SMEM_BYTES>>>(
        p_ah, p_al, p_woh, p_wol, bout, p_o2, HDIM, HDIM);                        // 8
    ln_kernel<<<BATCH, 256>>>(p_o2, p_xh, p_xl, gamma, beta, out);                // 9

    (void)in_sizes; (void)n_in; (void)out_size;
}

// round 12
// speedup vs baseline: 1.0614x; 1.0614x over previous
#include <cuda_runtime.h>
#include <cuda_bf16.h>
#include <stdint.h>
#include <math.h>

// ---------------------------------------------------------------------------
// MultiModalAttention (sm_103 base target): HMMA m16n8k16 bf16, 3-term split.
// Round 12: R10 GEMM core verbatim (best: 1547us). Small-kernel fixes only:
// vectorized wsplit (bf16x2 stores, 64x32 tiles) and vectorized LayerNorm.
// ---------------------------------------------------------------------------

#define BATCH   8192
#define IMGDIM  2048
#define QDIM    768
#define HDIM    1024
#define H3      3072
#define B2      16384
#define NHEADS  16
#define HD      64

#define BM 256
#define BN 128
#define BK 32
#define KS_BYTES 80
#define ARR_A (BM * KS_BYTES)             // 20480
#define ARR_B (BN * KS_BYTES)             // 10240
#define OFF_AH 0
#define OFF_AL (ARR_A)
#define OFF_BH (2 * ARR_A)
#define OFF_BL (2 * ARR_A + ARR_B)
#define STAGE_BYTES (2 * ARR_A + 2 * ARR_B)   // 61440
#define NSTAGE 3
#define SMEM_BYTES (NSTAGE * STAGE_BYTES)     // 184320

// ---------------- device scratch ---------------------------------------------
__device__ float g_qkv[(size_t)B2 * H3];
__device__ float g_o2 [(size_t)B2 * HDIM];

__device__ __nv_bfloat16 g_f1h[(size_t)BATCH * IMGDIM], g_f1l[(size_t)BATCH * IMGDIM];
__device__ __nv_bfloat16 g_f2h[(size_t)BATCH * QDIM],  g_f2l[(size_t)BATCH * QDIM];
__device__ __nv_bfloat16 g_xh [(size_t)B2 * HDIM],     g_xl [(size_t)B2 * HDIM];
__device__ __nv_bfloat16 g_ah [(size_t)B2 * HDIM],     g_al [(size_t)B2 * HDIM];
__device__ __nv_bfloat16 g_w1h[(size_t)HDIM * IMGDIM], g_w1l[(size_t)HDIM * IMGDIM];
__device__ __nv_bfloat16 g_w2h[(size_t)HDIM * QDIM],   g_w2l[(size_t)HDIM * QDIM];
__device__ __nv_bfloat16 g_wqh[(size_t)H3 * HDIM],     g_wql[(size_t)H3 * HDIM];
__device__ __nv_bfloat16 g_woh[(size_t)HDIM * HDIM],   g_wol[(size_t)HDIM * HDIM];

// ---------------- helpers ------------------------------------------------------
__device__ __forceinline__ uint32_t smem_u32(const void* p) {
    return (uint32_t)__cvta_generic_to_shared(p);
}
__device__ __forceinline__ void cp16(uint32_t s, const void* g) {
    asm volatile("cp.async.cg.shared.global [%0], [%1], 16;"
                 :: "r"(s), "l"(__cvta_generic_to_global(g)) : "memory");
}
#define LDMX4(r, addr) \
    asm volatile("ldmatrix.sync.aligned.m8n8.x4.shared.b16 {%0,%1,%2,%3}, [%4];" \
        : "=r"((r)[0]), "=r"((r)[1]), "=r"((r)[2]), "=r"((r)[3]) : "r"(addr))
#define MMA16816(c, a, b0, b1) \
    asm volatile("mma.sync.aligned.m16n8k16.row.col.f32.bf16.bf16.f32 " \
        "{%0,%1,%2,%3}, {%4,%5,%6,%7}, {%8,%9}, {%0,%1,%2,%3};" \
        : "+f"((c)[0]), "+f"((c)[1]), "+f"((c)[2]), "+f"((c)[3]) \
        : "r"((a)[0]), "r"((a)[1]), "r"((a)[2]), "r"((a)[3]), "r"(b0), "r"(b1))

// ---------------- stage loader (512 threads, 6 cp.async each) -----------------
__device__ __forceinline__ void load_stage(
    uint32_t st, int tid,
    const __nv_bfloat16* __restrict__ Ah, const __nv_bfloat16* __restrict__ Al,
    const __nv_bfloat16* __restrict__ Bh, const __nv_bfloat16* __restrict__ Bl,
    int bm, int bn, int K, int k0)
{
    const int q  = tid & 3;
    const int rb = tid >> 2;     // 0..127
    #pragma unroll
    for (int t = 0; t < 6; t++) {
        const __nv_bfloat16* g;
        uint32_t sa;
        if (t < 2) {
            const int r = t * 128 + rb;
            g  = Ah + (size_t)(bm + r) * K + k0 + q * 8;
            sa = st + OFF_AH + (uint32_t)r * KS_BYTES + q * 16;
        } else if (t < 4) {
            const int r = (t - 2) * 128 + rb;
            g  = Al + (size_t)(bm + r) * K + k0 + q * 8;
            sa = st + OFF_AL + (uint32_t)r * KS_BYTES + q * 16;
        } else if (t == 4) {
            g  = Bh + (size_t)(bn + rb) * K + k0 + q * 8;
            sa = st + OFF_BH + (uint32_t)rb * KS_BYTES + q * 16;
        } else {
            g  = Bl + (size_t)(bn + rb) * K + k0 + q * 8;
            sa = st + OFF_BL + (uint32_t)rb * KS_BYTES + q * 16;
        }
        cp16(sa, g);
    }
    asm volatile("cp.async.commit_group;" ::: "memory");
}

// ---------------- shared GEMM body (R6/R10 schedule, verbatim) ------------------
__device__ __forceinline__ void gemm_body(
    const __nv_bfloat16* __restrict__ Ah, const __nv_bfloat16* __restrict__ Al,
    const __nv_bfloat16* __restrict__ Bh, const __nv_bfloat16* __restrict__ Bl,
    const float* __restrict__ bias,
    float* __restrict__ outF, __nv_bfloat16* __restrict__ outH,
    __nv_bfloat16* __restrict__ outL,
    int N, int K, int row_mul, int row_off, int bm, int bn, uint32_t sb)
{
    const int tid   = threadIdx.x;
    const int wid   = tid >> 5;
    const int lane  = tid & 31;
    const int warpM = wid >> 2;      // 0..3 -> 64 rows each
    const int warpN = wid & 3;       // 0..3 -> 32 cols each

    float c[4][4][4];                // 64 regs
    #pragma unroll
    for (int i = 0; i < 4; i++)
        #pragma unroll
        for (int j = 0; j < 4; j++)
            #pragma unroll
            for (int k = 0; k < 4; k++) c[i][j][k] = 0.0f;

    const int NT = K / BK;
    load_stage(sb,               tid, Ah, Al, Bh, Bl, bm, bn, K, 0);
    load_stage(sb + STAGE_BYTES, tid, Ah, Al, Bh, Bl, bm, bn, K, BK);

    const int g8 = lane >> 3, lr = lane & 7;
    const int a_row = warpM * 64 + ((g8 & 1) ? 8 : 0) + lr;   // + mt*16
    const int a_kb  = (g8 >> 1) ? 16 : 0;
    const int b_row = warpN * 32 + ((g8 >> 1) ? 8 : 0) + lr;  // + n16*16
    const int b_kb  = (g8 & 1) ? 16 : 0;

    for (int kt = 0; kt < NT; kt++) {
        if (kt + 1 < NT) asm volatile("cp.async.wait_group 1;" ::: "memory");
        else             asm volatile("cp.async.wait_group 0;" ::: "memory");
        __syncthreads();

        const uint32_t st = sb + (uint32_t)(kt % NSTAGE) * STAGE_BYTES;
        #pragma unroll
        for (int kk = 0; kk < 2; kk++) {
            const int kb = kk * 32;
            uint32_t ah[4][4], al[4][4];
            #pragma unroll
            for (int mt = 0; mt < 4; mt++) {
                uint32_t aaddr = st + OFF_AH +
                    (uint32_t)(a_row + mt * 16) * KS_BYTES + a_kb + kb;
                LDMX4(ah[mt], aaddr);
                LDMX4(al[mt], aaddr + ARR_A);
            }
            #pragma unroll
            for (int n16 = 0; n16 < 2; n16++) {
                uint32_t baddr = st + OFF_BH +
                    (uint32_t)(b_row + n16 * 16) * KS_BYTES + b_kb + kb;
                uint32_t bh[4], bl[4];
                LDMX4(bh, baddr);
                LDMX4(bl, baddr + ARR_B);
                #pragma unroll
                for (int mt = 0; mt < 4; mt++)
                    #pragma unroll
                    for (int nn = 0; nn < 2; nn++)
                        MMA16816(c[mt][n16 * 2 + nn], ah[mt], bh[2*nn], bh[2*nn+1]);
                #pragma unroll
                for (int mt = 0; mt < 4; mt++)
                    #pragma unroll
                    for (int nn = 0; nn < 2; nn++)
                        MMA16816(c[mt][n16 * 2 + nn], ah[mt], bl[2*nn], bl[2*nn+1]);
                #pragma unroll
                for (int mt = 0; mt < 4; mt++)
                    #pragma unroll
                    for (int nn = 0; nn < 2; nn++)
                        MMA16816(c[mt][n16 * 2 + nn], al[mt], bh[2*nn], bh[2*nn+1]);
            }
        }
        if (kt + 2 < NT)
            load_stage(sb + (uint32_t)((kt + 2) % NSTAGE) * STAGE_BYTES,
                       tid, Ah, Al, Bh, Bl, bm, bn, K, (kt + 2) * BK);
    }

    // ---- epilogue ----
    const int quad = lane >> 2;
    const int tq   = lane & 3;
    #pragma unroll
    for (int nt = 0; nt < 4; nt++) {
        const int col = bn + warpN * 32 + nt * 8 + tq * 2;
        float bv0 = 0.0f, bv1 = 0.0f;
        if (bias) { bv0 = bias[col]; bv1 = bias[col + 1]; }
        #pragma unroll
        for (int mt = 0; mt < 4; mt++) {
            #pragma unroll
            for (int half = 0; half < 2; half++) {
                const int grow = bm + warpM * 64 + mt * 16 + half * 8 + quad;
                const size_t off = ((size_t)grow * row_mul + row_off) * N + col;
                float v0 = c[mt][nt][2 * half + 0] + bv0;
                float v1 = c[mt][nt][2 * half + 1] + bv1;
                if (outF) *(float2*)(outF + off) = make_float2(v0, v1);
                if (outH) {
                    __nv_bfloat16 h0 = __float2bfloat16(v0);
                    __nv_bfloat16 h1 = __float2bfloat16(v1);
                    __nv_bfloat162 hp; hp.x = h0; hp.y = h1;
                    *(__nv_bfloat162*)(outH + off) = hp;
                    __nv_bfloat162 lp;
                    lp.x = __float2bfloat16(v0 - __bfloat162float(h0));
                    lp.y = __float2bfloat16(v1 - __bfloat162float(h1));
                    *(__nv_bfloat162*)(outL + off) = lp;
                }
            }
        }
    }
}

// ---------------- GEMM kernels -------------------------------------------------
__global__ void __launch_bounds__(512, 1)
gemm_hmma(const __nv_bfloat16* __restrict__ Ah, const __nv_bfloat16* __restrict__ Al,
          const __nv_bfloat16* __restrict__ Bh, const __nv_bfloat16* __restrict__ Bl,
          const float* __restrict__ bias, float* __restrict__ outF,
          int N, int K)
{
    extern __shared__ char smem[];
    gemm_body(Ah, Al, Bh, Bl, bias, outF, nullptr, nullptr,
              N, K, 1, 0, blockIdx.y * BM, blockIdx.x * BN, smem_u32(smem));
}

// merged f1/f2 projection: blockIdx.z = modality
__global__ void __launch_bounds__(512, 1)
gemm_proj(const __nv_bfloat16* __restrict__ f1h, const __nv_bfloat16* __restrict__ f1l,
          const __nv_bfloat16* __restrict__ w1h, const __nv_bfloat16* __restrict__ w1l,
          const float* __restrict__ b1,
          const __nv_bfloat16* __restrict__ f2h, const __nv_bfloat16* __restrict__ f2l,
          const __nv_bfloat16* __restrict__ w2h, const __nv_bfloat16* __restrict__ w2l,
          const float* __restrict__ b2,
          __nv_bfloat16* __restrict__ xh, __nv_bfloat16* __restrict__ xl)
{
    extern __shared__ char smem[];
    if (blockIdx.z == 0)
        gemm_body(f1h, f1l, w1h, w1l, b1, nullptr, xh, xl,
                  HDIM, IMGDIM, 2, 0, blockIdx.y * BM, blockIdx.x * BN,
                  smem_u32(smem));
    else
        gemm_body(f2h, f2l, w2h, w2l, b2, nullptr, xh, xl,
                  HDIM, QDIM, 2, 1, blockIdx.y * BM, blockIdx.x * BN,
                  smem_u32(smem));
}

// ---------------- elementwise split (activations) ----------------------------
__global__ void __launch_bounds__(256)
asplit(const float* __restrict__ x, __nv_bfloat16* __restrict__ h,
       __nv_bfloat16* __restrict__ l, size_t n)
{
    size_t i = ((size_t)blockIdx.x * 256 + threadIdx.x) * 4;
    if (i >= n) return;
    float4 v = *(const float4*)(x + i);
    __nv_bfloat16 h0 = __float2bfloat16(v.x), h1 = __float2bfloat16(v.y);
    __nv_bfloat16 h2 = __float2bfloat16(v.z), h3 = __float2bfloat16(v.w);
    __nv_bfloat162 hp0; hp0.x = h0; hp0.y = h1;
    __nv_bfloat162 hp1; hp1.x = h2; hp1.y = h3;
    *(__nv_bfloat162*)(h + i)     = hp0;
    *(__nv_bfloat162*)(h + i + 2) = hp1;
    __nv_bfloat162 lp0, lp1;
    lp0.x = __float2bfloat16(v.x - __bfloat162float(h0));
    lp0.y = __float2bfloat16(v.y - __bfloat162float(h1));
    lp1.x = __float2bfloat16(v.z - __bfloat162float(h2));
    lp1.y = __float2bfloat16(v.w - __bfloat162float(h3));
    *(__nv_bfloat162*)(l + i)     = lp0;
    *(__nv_bfloat162*)(l + i + 2) = lp1;
}

// ---------------- weight transpose+split, vectorized ---------------------------
// 64k x 32n tile per block; each thread emits bf16x2 (2 consecutive k).
// Block: (32, 8). Load: 64 rows x 32 cols coalesced float. Store: bf16x2
// rows of T[n][k], 32 threads x 4B = 128B coalesced.
__global__ void __launch_bounds__(256)
wsplit_v2(const float* __restrict__ W1, const float* __restrict__ W2,
          const float* __restrict__ Wq, const float* __restrict__ Wo,
          __nv_bfloat16* __restrict__ w1h, __nv_bfloat16* __restrict__ w1l,
          __nv_bfloat16* __restrict__ w2h, __nv_bfloat16* __restrict__ w2l,
          __nv_bfloat16* __restrict__ wqh, __nv_bfloat16* __restrict__ wql,
          __nv_bfloat16* __restrict__ woh, __nv_bfloat16* __restrict__ wol,
          int zbase)
{
    const float* W; __nv_bfloat16 *th, *tl; int K, N;
    switch (blockIdx.z + zbase) {
        case 0: W = W1; th = w1h; tl = w1l; K = IMGDIM; N = HDIM; break;
        case 1: W = W2; th = w2h; tl = w2l; K = QDIM;   N = HDIM; break;
        case 2: W = Wq; th = wqh; tl = wql; K = HDIM;   N = H3;   break;
        default:W = Wo; th = woh; tl = wol; K = HDIM;   N = HDIM; break;
    }
    const int n0 = blockIdx.x * 32, k0 = blockIdx.y * 64;
    if (n0 >= N || k0 >= K) return;

    __shared__ float tile[64][33];
    const int tx = threadIdx.x & 31, ty = threadIdx.x >> 5;   // (32, 8)
    #pragma unroll
    for (int i = ty; i < 64; i += 8)
        tile[i][tx] = W[(size_t)(k0 + i) * N + n0 + tx];
    __syncthreads();
    // store: thread tx -> k pair (2tx, 2tx+1); ty+8*i -> n offset
    #pragma unroll
    for (int i = 0; i < 4; i++) {
        const int nn = ty + i * 8;
        const int n = n0 + nn;
        float v0 = tile[2 * tx + 0][nn];
        float v1 = tile[2 * tx + 1][nn];
        __nv_bfloat16 h0 = __float2bfloat16(v0);
        __nv_bfloat16 h1 = __float2bfloat16(v1);
        __nv_bfloat162 hp; hp.x = h0; hp.y = h1;
        __nv_bfloat162 lp;
        lp.x = __float2bfloat16(v0 - __bfloat162float(h0));
        lp.y = __float2bfloat16(v1 - __bfloat162float(h1));
        const size_t off = (size_t)n * K + k0 + 2 * tx;
        *(__nv_bfloat162*)(th + off) = hp;
        *(__nv_bfloat162*)(tl + off) = lp;
    }
}

// ---------------- attention (2x2 per head) + split output --------------------
__global__ void __launch_bounds__(128)
attn_kernel(const float* __restrict__ qkv, __nv_bfloat16* __restrict__ oh,
            __nv_bfloat16* __restrict__ ol)
{
    const int b = blockIdx.x;
    const int warp = threadIdx.x >> 5;
    const int lane = threadIdx.x & 31;
    const float scale = 0.125f;
    const size_t base0 = (size_t)(2 * b) * H3;
    const size_t base1 = base0 + H3;

    #pragma unroll
    for (int h = warp; h < NHEADS; h += 4) {
        const int off = h * HD + lane;
        float q0a = qkv[base0 + off],          q0b = qkv[base0 + off + 32];
        float k0a = qkv[base0 + HDIM + off],   k0b = qkv[base0 + HDIM + off + 32];
        float v0a = qkv[base0 + 2*HDIM + off], v0b = qkv[base0 + 2*HDIM + off + 32];
        float q1a = qkv[base1 + off],          q1b = qkv[base1 + off + 32];
        float k1a = qkv[base1 + HDIM + off],   k1b = qkv[base1 + HDIM + off + 32];
        float v1a = qkv[base1 + 2*HDIM + off], v1b = qkv[base1 + 2*HDIM + off + 32];

        float s00 = q0a * k0a + q0b * k0b;
        float s01 = q0a * k1a + q0b * k1b;
        float s10 = q1a * k0a + q1b * k0b;
        float s11 = q1a * k1a + q1b * k1b;
        #pragma unroll
        for (int d = 16; d; d >>= 1) {
            s00 += __shfl_xor_sync(0xffffffffu, s00, d);
            s01 += __shfl_xor_sync(0xffffffffu, s01, d);
            s10 += __shfl_xor_sync(0xffffffffu, s10, d);
            s11 += __shfl_xor_sync(0xffffffffu, s11, d);
        }
        s00 *= scale; s01 *= scale; s10 *= scale; s11 *= scale;

        float m0 = fmaxf(s00, s01), m1 = fmaxf(s10, s11);
        float e00 = __expf(s00 - m0), e01 = __expf(s01 - m0);
        float e10 = __expf(s10 - m1), e11 = __expf(s11 - m1);
        float inv0 = 1.0f / (e00 + e01), inv1 = 1.0f / (e10 + e11);
        float p00 = e00 * inv0, p01 = e01 * inv0;
        float p10 = e10 * inv1, p11 = e11 * inv1;

        float r0 = p00 * v0a + p01 * v1a;
        float r1 = p00 * v0b + p01 * v1b;
        float r2 = p10 * v0a + p11 * v1a;
        float r3 = p10 * v0b + p11 * v1b;

        size_t o0 = (size_t)(2 * b) * HDIM + h * HD + lane;
        size_t o1 = o0 + HDIM;
        __nv_bfloat16 h0 = __float2bfloat16(r0);
        __nv_bfloat16 h1 = __float2bfloat16(r1);
        __nv_bfloat16 h2 = __float2bfloat16(r2);
        __nv_bfloat16 h3 = __float2bfloat16(r3);
        oh[o0] = h0;      oh[o0 + 32] = h1;
        oh[o1] = h2;      oh[o1 + 32] = h3;
        ol[o0]      = __float2bfloat16(r0 - __bfloat162float(h0));
        ol[o0 + 32] = __float2bfloat16(r1 - __bfloat162float(h1));
        ol[o1]      = __float2bfloat16(r2 - __bfloat162float(h2));
        ol[o1 + 32] = __float2bfloat16(r3 - __bfloat162float(h3));
    }
}

// ---------------- LayerNorm(2048) + residual(hi+lo), vectorized ----------------
__global__ void __launch_bounds__(256)
ln_kernel(const float* __restrict__ o2,
          const __nv_bfloat16* __restrict__ xh, const __nv_bfloat16* __restrict__ xl,
          const float* __restrict__ gamma, const float* __restrict__ beta,
          float* __restrict__ out)
{
    const int b = blockIdx.x;
    const int tid = threadIdx.x;
    const float4* x4 = (const float4*)(o2 + (size_t)b * 2048);

    float4 vals[2];
    float sum = 0.0f, sq = 0.0f;
    #pragma unroll
    for (int j = 0; j < 2; j++) {
        float4 v = x4[tid + j * 256];
        vals[j] = v;
        sum += v.x + v.y + v.z + v.w;
        sq  += v.x * v.x + v.y * v.y + v.z * v.z + v.w * v.w;
    }
    #pragma unroll
    for (int d = 16; d; d >>= 1) {
        sum += __shfl_xor_sync(0xffffffffu, sum, d);
        sq  += __shfl_xor_sync(0xffffffffu, sq, d);
    }
    __shared__ float ssum[8], ssq[8];
    const int warp = tid >> 5, lane = tid & 31;
    if (lane == 0) { ssum[warp] = sum; ssq[warp] = sq; }
    __syncthreads();
    float tsum = 0.0f, tsq = 0.0f;
    #pragma unroll
    for (int w = 0; w < 8; w++) { tsum += ssum[w]; tsq += ssq[w]; }

    const float mu   = tsum * (1.0f / 2048.0f);
    const float var  = tsq * (1.0f / 2048.0f) - mu * mu;
    const float rinv = rsqrtf(var + 1e-5f);

    const __nv_bfloat162* rh2 = (const __nv_bfloat162*)(xh + (size_t)b * 2048);
    const __nv_bfloat162* rl2 = (const __nv_bfloat162*)(xl + (size_t)b * 2048);
    const float4* g4 = (const float4*)gamma;
    const float4* bt4 = (const float4*)beta;
    float4* o4 = (float4*)(out + (size_t)b * 2048);
    #pragma unroll
    for (int j = 0; j < 2; j++) {
        const int c4 = tid + j * 256;         // float4 index
        float4 g = g4[c4], bt = bt4[c4];
        __nv_bfloat162 rh0 = rh2[2 * c4], rh1 = rh2[2 * c4 + 1];
        __nv_bfloat162 rl0 = rl2[2 * c4], rl1 = rl2[2 * c4 + 1];
        float4 v = vals[j];
        float4 o;
        o.x = (v.x - mu) * rinv * g.x + bt.x +
              __bfloat162float(rh0.x) + __bfloat162float(rl0.x);
        o.y = (v.y - mu) * rinv * g.y + bt.y +
              __bfloat162float(rh0.y) + __bfloat162float(rl0.y);
        o.z = (v.z - mu) * rinv * g.z + bt.z +
              __bfloat162float(rh1.x) + __bfloat162float(rl1.x);
        o.w = (v.w - mu) * rinv * g.w + bt.w +
              __bfloat162float(rh1.y) + __bfloat162float(rl1.y);
        o4[c4] = o;
    }
}

// ---------------------------------------------------------------------------
extern "C" void kernel_launch(void* const* d_in, const int* in_sizes, int n_in,
                              void* d_out, int out_size)
{
    const float* features1 = (const float*)d_in[0];
    const float* features2 = (const float*)d_in[1];
    const float* W1    = (const float*)d_in[2];
    const float* b1    = (const float*)d_in[3];
    const float* W2    = (const float*)d_in[4];
    const float* b2    = (const float*)d_in[5];
    const float* Wqkv  = (const float*)d_in[6];
    const float* Wout  = (const float*)d_in[7];
    const float* bout  = (const float*)d_in[8];
    const float* gamma = (const float*)d_in[9];
    const float* beta  = (const float*)d_in[10];
    float* out = (float*)d_out;

    float *p_qkv, *p_o2;
    __nv_bfloat16 *p_f1h, *p_f1l, *p_f2h, *p_f2l, *p_xh, *p_xl, *p_ah, *p_al;
    __nv_bfloat16 *p_w1h, *p_w1l, *p_w2h, *p_w2l, *p_wqh, *p_wql, *p_woh, *p_wol;
    cudaGetSymbolAddress((void**)&p_qkv, g_qkv);
    cudaGetSymbolAddress((void**)&p_o2,  g_o2);
    cudaGetSymbolAddress((void**)&p_f1h, g_f1h); cudaGetSymbolAddress((void**)&p_f1l, g_f1l);
    cudaGetSymbolAddress((void**)&p_f2h, g_f2h); cudaGetSymbolAddress((void**)&p_f2l, g_f2l);
    cudaGetSymbolAddress((void**)&p_xh,  g_xh);  cudaGetSymbolAddress((void**)&p_xl,  g_xl);
    cudaGetSymbolAddress((void**)&p_ah,  g_ah);  cudaGetSymbolAddress((void**)&p_al,  g_al);
    cudaGetSymbolAddress((void**)&p_w1h, g_w1h); cudaGetSymbolAddress((void**)&p_w1l, g_w1l);
    cudaGetSymbolAddress((void**)&p_w2h, g_w2h); cudaGetSymbolAddress((void**)&p_w2l, g_w2l);
    cudaGetSymbolAddress((void**)&p_wqh, g_wqh); cudaGetSymbolAddress((void**)&p_wql, g_wql);
    cudaGetSymbolAddress((void**)&p_woh, g_woh); cudaGetSymbolAddress((void**)&p_wol, g_wol);

    cudaFuncSetAttribute(gemm_hmma, cudaFuncAttributeMaxDynamicSharedMemorySize,
                         SMEM_BYTES);
    cudaFuncSetAttribute(gemm_proj, cudaFuncAttributeMaxDynamicSharedMemorySize,
                         SMEM_BYTES);

    // ncu (-s 5 -c 1) captures our 4th launch -> keep proj there.
    asplit<<<(size_t)BATCH * IMGDIM / 1024, 256>>>(features1, p_f1h, p_f1l,
                                                   (size_t)BATCH * IMGDIM);       // 1
    asplit<<<(size_t)BATCH * QDIM / 1024, 256>>>(features2, p_f2h, p_f2l,
                                                 (size_t)BATCH * QDIM);           // 2
    wsplit_v2<<<dim3(HDIM / 32, IMGDIM / 64, 2), 256>>>(
        W1, W2, Wqkv, Wout, p_w1h, p_w1l, p_w2h, p_w2l,
        p_wqh, p_wql, p_woh, p_wol, 0);                                           // 3
    // merged f1/f2 projections -> x hi/lo (profiled launch)
    gemm_proj<<<dim3(HDIM / BN, BATCH / BM, 2), 512, SMEM_BYTES>>>(
        p_f1h, p_f1l, p_w1h, p_w1l, b1,
        p_f2h, p_f2l, p_w2h, p_w2l, b2, p_xh, p_xl);                              // 4
    wsplit_v2<<<dim3(H3 / 32, HDIM / 64, 2), 256>>>(
        W1, W2, Wqkv, Wout, p_w1h, p_w1l, p_w2h, p_w2l,
        p_wqh, p_wql, p_woh, p_wol, 2);                                           // 5
    // G3: x @ Wqkv -> qkv fp32
    gemm_hmma<<<dim3(H3 / BN, B2 / BM), 512, SMEM_BYTES>>>(
        p_xh, p_xl, p_wqh, p_wql, nullptr, p_qkv, H3, HDIM);                      // 6
    attn_kernel<<<BATCH, 128>>>(p_qkv, p_ah, p_al);                               // 7
    // G4: att @ Wout + bout -> o2 fp32
    gemm_hmma<<<dim3(HDIM / BN, B2 / BM), 512, SMEM_BYTES>>>(
        p_ah, p_al, p_woh, p_wol, bout, p_o2, HDIM, HDIM);                        // 8
    ln_kernel<<<BATCH, 256>>>(p_o2, p_xh, p_xl, gamma, beta, out);                // 9

    (void)in_sizes; (void)n_in; (void)out_size;
}